// round 15
// baseline (speedup 1.0000x reference)
#include <cuda_runtime.h>
#include <cuda_bf16.h>
#include <cstdint>
#include <cstddef>

constexpr int NN = 4096;   // nodes
constexpr int DD = 512;    // feature dim

// ---------------- device scratch (allocation-free; ONLY referenced in-kernel) --
__device__ __align__(256) __nv_bfloat16 g_Ahi[(size_t)NN * NN];   // bf16 split of A+I
__device__ __align__(256) __nv_bfloat16 g_Alo[(size_t)NN * NN];
__device__ __align__(256) __nv_bfloat16 g_Xt_hi[(size_t)DD * NN]; // X^T split [512,4096]
__device__ __align__(256) __nv_bfloat16 g_Xt_lo[(size_t)DD * NN];
__device__ __align__(256) __nv_bfloat16 g_Whi[(size_t)DD * DD];   // W split (already [N,K])
__device__ __align__(256) __nv_bfloat16 g_Wlo[(size_t)DD * DD];
__device__ __align__(256) __nv_bfloat16 g_Yhi[(size_t)NN * DD];   // Y = A2@X split
__device__ __align__(256) __nv_bfloat16 g_Ylo[(size_t)NN * DD];
__device__ __align__(256) float         g_Ts [(size_t)NN * DD];   // ds.*(Y@W^T) fp32
__device__ __align__(256) __nv_bfloat16 g_Tst_hi[(size_t)DD * NN]; // Ts^T split
__device__ __align__(256) __nv_bfloat16 g_Tst_lo[(size_t)DD * NN];
__device__ __align__(256) float         g_ds [NN];

// ---------------- PTX helpers ----------------
__device__ __forceinline__ uint32_t smem_u32(const void* p) {
    uint32_t a;
    asm("{ .reg .u64 t; cvta.to.shared.u64 t, %1; cvt.u32.u64 %0, t; }" : "=r"(a) : "l"(p));
    return a;
}
__device__ __forceinline__ void cp16(uint32_t dst, const void* src) {
    asm volatile("cp.async.cg.shared.global [%0], [%1], 16;" :: "r"(dst), "l"(src));
}
__device__ __forceinline__ void cp_commit() { asm volatile("cp.async.commit_group;"); }
template <int N> __device__ __forceinline__ void cp_wait() {
    asm volatile("cp.async.wait_group %0;" :: "n"(N));
}
__device__ __forceinline__ void ldsm4(uint32_t& r0, uint32_t& r1, uint32_t& r2, uint32_t& r3,
                                      uint32_t addr) {
    asm volatile("ldmatrix.sync.aligned.m8n8.x4.shared.b16 {%0,%1,%2,%3}, [%4];"
                 : "=r"(r0), "=r"(r1), "=r"(r2), "=r"(r3) : "r"(addr));
}
__device__ __forceinline__ void mma16816(float* d, const uint32_t* a, const uint32_t* b) {
    asm volatile(
        "mma.sync.aligned.m16n8k16.row.col.f32.bf16.bf16.f32 "
        "{%0,%1,%2,%3},{%4,%5,%6,%7},{%8,%9},{%0,%1,%2,%3};"
        : "+f"(d[0]), "+f"(d[1]), "+f"(d[2]), "+f"(d[3])
        : "r"(a[0]), "r"(a[1]), "r"(a[2]), "r"(a[3]), "r"(b[0]), "r"(b[1]));
}

// ---------------- preprocessing (globals referenced IN-BODY only) ----------
__global__ void dscale_kernel(const float* __restrict__ A) {
    int i = blockIdx.x * blockDim.x + threadIdx.x;
    if (i < NN) g_ds[i] = rsqrtf(A[(size_t)i * NN + i] + 1.0f);
}

__global__ void conv_A_kernel(const float* __restrict__ A) {
    size_t base = ((size_t)blockIdx.x * blockDim.x + threadIdx.x) * 4;
    if (base >= (size_t)NN * NN) return;
    float4 v = *(const float4*)(A + base);
    int row = (int)(base >> 12);
    int col = (int)(base & (NN - 1));
    int d = row - col;
    if (d >= 0 && d < 4) ((float*)&v)[d] += 1.0f;
    float* vp = (float*)&v;
    __nv_bfloat16 h[4], l[4];
    #pragma unroll
    for (int k = 0; k < 4; k++) {
        h[k] = __float2bfloat16(vp[k]);
        l[k] = __float2bfloat16(vp[k] - __bfloat162float(h[k]));
    }
    *(__nv_bfloat162*)(g_Ahi + base)     = __halves2bfloat162(h[0], h[1]);
    *(__nv_bfloat162*)(g_Ahi + base + 2) = __halves2bfloat162(h[2], h[3]);
    *(__nv_bfloat162*)(g_Alo + base)     = __halves2bfloat162(l[0], l[1]);
    *(__nv_bfloat162*)(g_Alo + base + 2) = __halves2bfloat162(l[2], l[3]);
}

__global__ void conv_W_kernel(const float* __restrict__ W) {
    size_t base = ((size_t)blockIdx.x * blockDim.x + threadIdx.x) * 4;
    if (base >= (size_t)DD * DD) return;
    float4 v = *(const float4*)(W + base);
    float* vp = (float*)&v;
    __nv_bfloat16 h[4], l[4];
    #pragma unroll
    for (int k = 0; k < 4; k++) {
        h[k] = __float2bfloat16(vp[k]);
        l[k] = __float2bfloat16(vp[k] - __bfloat162float(h[k]));
    }
    *(__nv_bfloat162*)(g_Whi + base)     = __halves2bfloat162(h[0], h[1]);
    *(__nv_bfloat162*)(g_Whi + base + 2) = __halves2bfloat162(h[2], h[3]);
    *(__nv_bfloat162*)(g_Wlo + base)     = __halves2bfloat162(l[0], l[1]);
    *(__nv_bfloat162*)(g_Wlo + base + 2) = __halves2bfloat162(l[2], l[3]);
}

// X^T split: X fp32 [NN, DD] -> g_Xt_{hi,lo} [DD, NN]
__global__ void tspX_kernel(const float* __restrict__ X) {
    __shared__ float tile[32][33];
    int bx = blockIdx.x, by = blockIdx.y;
    int x = threadIdx.x, y0 = threadIdx.y;
    #pragma unroll
    for (int yy = 0; yy < 32; yy += 8)
        tile[y0 + yy][x] = X[(size_t)(by * 32 + y0 + yy) * DD + bx * 32 + x];
    __syncthreads();
    #pragma unroll
    for (int yy = 0; yy < 32; yy += 8) {
        int orow = bx * 32 + y0 + yy;
        int oc   = by * 32 + x;
        float v = tile[x][y0 + yy];
        __nv_bfloat16 h = __float2bfloat16(v);
        __nv_bfloat16 l = __float2bfloat16(v - __bfloat162float(h));
        g_Xt_hi[(size_t)orow * NN + oc] = h;
        g_Xt_lo[(size_t)orow * NN + oc] = l;
    }
}

// Ts^T split: g_Ts fp32 [NN, DD] -> g_Tst_{hi,lo} [DD, NN]
__global__ void tspT_kernel() {
    __shared__ float tile[32][33];
    int bx = blockIdx.x, by = blockIdx.y;
    int x = threadIdx.x, y0 = threadIdx.y;
    #pragma unroll
    for (int yy = 0; yy < 32; yy += 8)
        tile[y0 + yy][x] = g_Ts[(size_t)(by * 32 + y0 + yy) * DD + bx * 32 + x];
    __syncthreads();
    #pragma unroll
    for (int yy = 0; yy < 32; yy += 8) {
        int orow = bx * 32 + y0 + yy;
        int oc   = by * 32 + x;
        float v = tile[x][y0 + yy];
        __nv_bfloat16 h = __float2bfloat16(v);
        __nv_bfloat16 l = __float2bfloat16(v - __bfloat162float(h));
        g_Tst_hi[(size_t)orow * NN + oc] = h;
        g_Tst_lo[(size_t)orow * NN + oc] = l;
    }
}

// ---------------- HMMA GEMM (R13-validated; fragment loads now ldmatrix) ----
constexpr int BK = 64;
constexpr int ROWB = 144;                    // 128B data + 16B pad per smem row
constexpr int TILE_BYTES  = 128 * ROWB;      // 18432 B
constexpr int STAGE_BYTES = 4 * TILE_BYTES;  // 73728 B
constexpr int NSTAGE = 3;
constexpr int SMEM_DYN = NSTAGE * STAGE_BYTES;   // 221184 B

__device__ __forceinline__ void split_store(size_t idx, float v0, float v1) {
    __nv_bfloat16 h0 = __float2bfloat16(v0);
    __nv_bfloat16 h1 = __float2bfloat16(v1);
    *(__nv_bfloat162*)(g_Yhi + idx) = __halves2bfloat162(h0, h1);
    *(__nv_bfloat162*)(g_Ylo + idx) = __halves2bfloat162(
        __float2bfloat16(v0 - __bfloat162float(h0)),
        __float2bfloat16(v1 - __bfloat162float(h1)));
}

// MODE 0: A=A2 split, B=Xt split,  K=4096 -> Y split
// MODE 1: A=Y  split, B=W  split,  K=512  -> g_Ts = ds.*acc
// MODE 2: A=A2 split, B=Tst split, K=4096 -> out = relu(ds.*acc)
template <int MODE>
__global__ void __launch_bounds__(256, 1)
hmma_gemm(float* __restrict__ out2)
{
    constexpr int K = (MODE == 1) ? DD : NN;
    constexpr int C = K / BK;

    const __nv_bfloat16* Ah = (MODE == 1) ? g_Yhi : g_Ahi;
    const __nv_bfloat16* Al = (MODE == 1) ? g_Ylo : g_Alo;
    const __nv_bfloat16* Bh = (MODE == 0) ? g_Xt_hi : (MODE == 1) ? g_Whi : g_Tst_hi;
    const __nv_bfloat16* Bl = (MODE == 0) ? g_Xt_lo : (MODE == 1) ? g_Wlo : g_Tst_lo;

    extern __shared__ char smem_raw[];
    const uint32_t sb32 = smem_u32(smem_raw);

    const int tid  = threadIdx.x;
    const int lane = tid & 31;
    const int wid  = tid >> 5;
    const int m0 = blockIdx.y * 128;
    const int n0 = blockIdx.x * 128;

    // async loader: group t = tid>>6 (0:Ah 1:Al 2:Bh 3:Bl), rows 2tt, 2tt+1
    const int t  = tid >> 6;
    const int tt = tid & 63;
    const __nv_bfloat16* src = (t == 0) ? Ah : (t == 1) ? Al : (t == 2) ? Bh : Bl;
    const int rbase = (t < 2) ? m0 : n0;
    const char* r0p = (const char*)(src + (size_t)(rbase + tt * 2) * K);
    const char* r1p = r0p + (size_t)K * 2;
    const uint32_t wdst0 = sb32 + (uint32_t)t * TILE_BYTES + (uint32_t)(tt * 2) * ROWB;
    const uint32_t wdst1 = wdst0 + ROWB;

    auto load_stage = [&](int stage, int c) {
        const uint32_t so = (uint32_t)stage * STAGE_BYTES;
        const char* g0 = r0p + (size_t)c * 128;
        const char* g1 = r1p + (size_t)c * 128;
        #pragma unroll
        for (int ch = 0; ch < 8; ch++) {
            cp16(so + wdst0 + ch * 16, g0 + ch * 16);
            cp16(so + wdst1 + ch * 16, g1 + ch * 16);
        }
    };

    #pragma unroll
    for (int i = 0; i < NSTAGE; i++) {
        if (i < C) load_stage(i, i);
        cp_commit();
    }

    // 8 warps = 2(m) x 4(n); warp tile 64x32
    const int wm = (wid >> 2) * 64;
    const int wn = (wid & 3) * 32;
    const int g  = lane >> 2;
    const int q  = lane & 3;
    // ldmatrix per-lane row addressing:
    //   lanes 0-15 -> rows (lane&15), offset +0 ; lanes 16-31 -> rows (lane&15), offset +16B
    const uint32_t lrow = (uint32_t)(lane & 15);
    const uint32_t lsel = (uint32_t)(lane >> 4) * 16;
    const uint32_t aanchor = (uint32_t)(wm + lrow) * ROWB + lsel;
    const uint32_t banchor = (uint32_t)(wn + lrow) * ROWB + lsel;

    float acc[4][4][4];
    #pragma unroll
    for (int a = 0; a < 4; a++)
        #pragma unroll
        for (int b = 0; b < 4; b++)
            #pragma unroll
            for (int r = 0; r < 4; r++) acc[a][b][r] = 0.0f;

    for (int c = 0; c < C; c++) {
        const int s = c % NSTAGE;
        cp_wait<NSTAGE - 1>();
        __syncthreads();
        const uint32_t stbu = sb32 + (uint32_t)s * STAGE_BYTES;
        const uint32_t uAh = stbu;
        const uint32_t uAl = stbu + TILE_BYTES;
        const uint32_t uBh = stbu + 2 * TILE_BYTES;
        const uint32_t uBl = stbu + 3 * TILE_BYTES;

        #pragma unroll
        for (int ks = 0; ks < 4; ks++) {
            const uint32_t kb = ks * 32;   // 16 bf16 = 32 bytes per k-step
            uint32_t ah[4][4], al[4][4], bh[4][2], bl[4][2];
            // A fragments: one ldmatrix.x4 per 16-row tile
            //   matrices: (m0-7,k) (m8-15,k) (m0-7,k+8) (m8-15,k+8) -> a0..a3
            #pragma unroll
            for (int mt = 0; mt < 4; mt++) {
                const uint32_t o = aanchor + (uint32_t)mt * (16 * ROWB) + kb;
                ldsm4(ah[mt][0], ah[mt][1], ah[mt][2], ah[mt][3], uAh + o);
                ldsm4(al[mt][0], al[mt][1], al[mt][2], al[mt][3], uAl + o);
            }
            // B fragments: one ldmatrix.x4 covers two adjacent n-tiles
            //   matrices: (n[2p],k) (n[2p+1],k) (n[2p],k+8) (n[2p+1],k+8)
            #pragma unroll
            for (int p = 0; p < 2; p++) {
                const uint32_t o = banchor + (uint32_t)p * (16 * ROWB) + kb;
                uint32_t r0, r1, r2, r3;
                ldsm4(r0, r1, r2, r3, uBh + o);
                bh[2 * p][0] = r0; bh[2 * p + 1][0] = r1;
                bh[2 * p][1] = r2; bh[2 * p + 1][1] = r3;
                ldsm4(r0, r1, r2, r3, uBl + o);
                bl[2 * p][0] = r0; bl[2 * p + 1][0] = r1;
                bl[2 * p][1] = r2; bl[2 * p + 1][1] = r3;
            }
            #pragma unroll
            for (int mt = 0; mt < 4; mt++)
                #pragma unroll
                for (int nt = 0; nt < 4; nt++) {
                    mma16816(acc[mt][nt], ah[mt], bh[nt]);
                    mma16816(acc[mt][nt], ah[mt], bl[nt]);
                    mma16816(acc[mt][nt], al[mt], bh[nt]);
                }
        }

        __syncthreads();
        if (c + NSTAGE < C) load_stage(s, c + NSTAGE);
        cp_commit();
    }

    // epilogue: d0=(g,2q) d1=(g,2q+1) d2=(g+8,2q) d3=(g+8,2q+1)
    const int l2 = q << 1;
    #pragma unroll
    for (int mt = 0; mt < 4; mt++) {
        const int r0 = m0 + wm + mt * 16 + g;
        const int r1 = r0 + 8;
        float ds0 = 1.0f, ds1 = 1.0f;
        if (MODE != 0) { ds0 = g_ds[r0]; ds1 = g_ds[r1]; }
        #pragma unroll
        for (int nt = 0; nt < 4; nt++) {
            const int cc = n0 + wn + nt * 8 + l2;
            const size_t i0 = (size_t)r0 * DD + cc;
            const size_t i1 = (size_t)r1 * DD + cc;
            const float* a = acc[mt][nt];
            if (MODE == 0) {
                split_store(i0, a[0], a[1]);
                split_store(i1, a[2], a[3]);
            } else if (MODE == 1) {
                *(float2*)(g_Ts + i0) = make_float2(a[0] * ds0, a[1] * ds0);
                *(float2*)(g_Ts + i1) = make_float2(a[2] * ds1, a[3] * ds1);
            } else {
                *(float2*)(out2 + i0) = make_float2(fmaxf(a[0] * ds0, 0.0f),
                                                    fmaxf(a[1] * ds0, 0.0f));
                *(float2*)(out2 + i1) = make_float2(fmaxf(a[2] * ds1, 0.0f),
                                                    fmaxf(a[3] * ds1, 0.0f));
            }
        }
    }
}

// ---------------- host launcher ----------------
extern "C" void kernel_launch(void* const* d_in, const int* in_sizes, int n_in,
                              void* d_out, int out_size)
{
    const float* X = (const float*)d_in[0];  // [4096, 512]
    const float* A = (const float*)d_in[1];  // [4096, 4096]
    const float* W = (const float*)d_in[2];  // [512, 512]
    float* out = (float*)d_out;              // [4096, 512]

    cudaFuncSetAttribute(hmma_gemm<0>, cudaFuncAttributeMaxDynamicSharedMemorySize, SMEM_DYN);
    cudaFuncSetAttribute(hmma_gemm<1>, cudaFuncAttributeMaxDynamicSharedMemorySize, SMEM_DYN);
    cudaFuncSetAttribute(hmma_gemm<2>, cudaFuncAttributeMaxDynamicSharedMemorySize, SMEM_DYN);

    dscale_kernel<<<(NN + 255) / 256, 256>>>(A);
    conv_A_kernel<<<(int)(((size_t)NN * NN / 4 + 255) / 256), 256>>>(A);
    {
        dim3 g(DD / 32, NN / 32), b(32, 8);
        tspX_kernel<<<g, b>>>(X);
    }
    conv_W_kernel<<<(int)(((size_t)DD * DD / 4 + 255) / 256), 256>>>(W);

    dim3 grid(DD / 128, NN / 128);  // (4, 32) = 128 CTAs
    hmma_gemm<0><<<grid, 256, SMEM_DYN>>>(nullptr);  // Y = A2 @ X (split)
    hmma_gemm<1><<<grid, 256, SMEM_DYN>>>(nullptr);  // Ts = ds .* (Y @ W^T)
    {
        dim3 g(DD / 32, NN / 32), b(32, 8);
        tspT_kernel<<<g, b>>>();
    }
    hmma_gemm<2><<<grid, 256, SMEM_DYN>>>(out);      // out = relu(ds .* (A2 @ Ts))
}

// round 17
// speedup vs baseline: 1.1098x; 1.1098x over previous
#include <cuda_runtime.h>
#include <cuda_bf16.h>
#include <cstdint>
#include <cstddef>

constexpr int NN = 4096;   // nodes
constexpr int DD = 512;    // feature dim

// ---------------- packed-layout geometry ----------------
// A-packed tile (128 rows x 64 k, bf16): 32 slots (ks*8+mtg) x 32 lanes x 16B = 16384 B
//   slot 16B = {a0,a1,a2,a3} for lane (g=l>>2, q=l&3):
//   a0=(r+g, c+2q..+1) a1=(r+g+8, ..) a2=(r+g, c+2q+8..) a3=(r+g+8, c+2q+8..)
// B-packed tile (128 n-rows x 64 k, bf16): 64 slots (ks*16+ntg) x 32 lanes x 8B = 16384 B
//   slot 8B = {b0,b1}: b0=(n+g, c+2q..+1) b1=(n+g, c+2q+8..+1)
constexpr int TILE_B = 16384;

// ---------------- device scratch (allocation-free; referenced in-kernel only) --
__device__ __align__(256) __nv_bfloat16 g_Ahi[(size_t)NN * NN];   // A2 packed-A
__device__ __align__(256) __nv_bfloat16 g_Alo[(size_t)NN * NN];
__device__ __align__(256) __nv_bfloat16 g_Xt_hi[(size_t)DD * NN]; // X^T packed-B
__device__ __align__(256) __nv_bfloat16 g_Xt_lo[(size_t)DD * NN];
__device__ __align__(256) __nv_bfloat16 g_Whi[(size_t)DD * DD];   // W packed-B
__device__ __align__(256) __nv_bfloat16 g_Wlo[(size_t)DD * DD];
__device__ __align__(256) __nv_bfloat16 g_Yhi[(size_t)NN * DD];   // Y packed-A
__device__ __align__(256) __nv_bfloat16 g_Ylo[(size_t)NN * DD];
__device__ __align__(256) float         g_Ts [(size_t)NN * DD];   // row-major fp32
__device__ __align__(256) __nv_bfloat16 g_Tst_hi[(size_t)DD * NN]; // Ts^T packed-B
__device__ __align__(256) __nv_bfloat16 g_Tst_lo[(size_t)DD * NN];
__device__ __align__(256) float         g_ds [NN];

// ---------------- PTX helpers ----------------
__device__ __forceinline__ uint32_t smem_u32(const void* p) {
    uint32_t a;
    asm("{ .reg .u64 t; cvta.to.shared.u64 t, %1; cvt.u32.u64 %0, t; }" : "=r"(a) : "l"(p));
    return a;
}
__device__ __forceinline__ void cp16(uint32_t dst, const void* src) {
    asm volatile("cp.async.cg.shared.global [%0], [%1], 16;" :: "r"(dst), "l"(src));
}
__device__ __forceinline__ void cp_commit() { asm volatile("cp.async.commit_group;"); }
template <int N> __device__ __forceinline__ void cp_wait() {
    asm volatile("cp.async.wait_group %0;" :: "n"(N));
}
__device__ __forceinline__ void mma16816(float* d, const uint32_t* a, const uint32_t* b) {
    asm volatile(
        "mma.sync.aligned.m16n8k16.row.col.f32.bf16.bf16.f32 "
        "{%0,%1,%2,%3},{%4,%5,%6,%7},{%8,%9},{%0,%1,%2,%3};"
        : "+f"(d[0]), "+f"(d[1]), "+f"(d[2]), "+f"(d[3])
        : "r"(a[0]), "r"(a[1]), "r"(a[2]), "r"(a[3]), "r"(b[0]), "r"(b[1]));
}
__device__ __forceinline__ uint32_t bf2_bits(__nv_bfloat162 v) {
    uint32_t r;
    __builtin_memcpy(&r, &v, 4);
    return r;
}
__device__ __forceinline__ uint32_t pk(float x, float y) {
    return bf2_bits(__halves2bfloat162(__float2bfloat16(x), __float2bfloat16(y)));
}
__device__ __forceinline__ uint32_t pklo(float x, float y) {
    float hx = __bfloat162float(__float2bfloat16(x));
    float hy = __bfloat162float(__float2bfloat16(y));
    return bf2_bits(__halves2bfloat162(__float2bfloat16(x - hx),
                                       __float2bfloat16(y - hy)));
}

// ---------------- preprocessing ----------------
// A2 = A + I -> packed-A bf16 hi/lo. 2M threads, one 16B hi + 16B lo slot each.
__global__ void conv_A_kernel(const float* __restrict__ A) {
    const uint32_t t = blockIdx.x * 256 + threadIdx.x;        // < 2,097,152
    const uint32_t l = t & 31, s = (t >> 5) & 31, tile = t >> 10;  // tile < 2048
    const uint32_t kc = tile & 63, mb = tile >> 6;
    const uint32_t g = l >> 2, q = l & 3, ks = s >> 3, mtg = s & 7;
    const uint32_t r0 = mb * 128 + mtg * 16 + g, r1 = r0 + 8;
    const uint32_t c0 = kc * 64 + ks * 16 + 2 * q;
    float2 v00 = *(const float2*)(A + (size_t)r0 * NN + c0);
    float2 v10 = *(const float2*)(A + (size_t)r1 * NN + c0);
    float2 v01 = *(const float2*)(A + (size_t)r0 * NN + c0 + 8);
    float2 v11 = *(const float2*)(A + (size_t)r1 * NN + c0 + 8);
    if (r0 == c0)     v00.x += 1.0f;
    if (r0 == c0 + 1) v00.y += 1.0f;
    if (r1 == c0)     v10.x += 1.0f;
    if (r1 == c0 + 1) v10.y += 1.0f;
    if (r0 == c0 + 8) v01.x += 1.0f;
    if (r0 == c0 + 9) v01.y += 1.0f;
    if (r1 == c0 + 8) v11.x += 1.0f;
    if (r1 == c0 + 9) v11.y += 1.0f;
    uint4 hi = make_uint4(pk(v00.x, v00.y), pk(v10.x, v10.y),
                          pk(v01.x, v01.y), pk(v11.x, v11.y));
    uint4 lo = make_uint4(pklo(v00.x, v00.y), pklo(v10.x, v10.y),
                          pklo(v01.x, v01.y), pklo(v11.x, v11.y));
    const size_t off = (size_t)tile * TILE_B + s * 512 + l * 16;
    *(uint4*)((char*)g_Ahi + off) = hi;
    *(uint4*)((char*)g_Alo + off) = lo;
}

// X^T -> packed-B hi/lo; tail blocks compute g_ds.
__global__ void prepXds_kernel(const float* __restrict__ X, const float* __restrict__ A) {
    if (blockIdx.x >= 2048) {
        int i = (blockIdx.x - 2048) * 256 + threadIdx.x;
        if (i < NN) g_ds[i] = rsqrtf(A[(size_t)i * NN + i] + 1.0f);
        return;
    }
    const uint32_t t = blockIdx.x * 256 + threadIdx.x;        // < 524,288
    const uint32_t l = t & 31, s = (t >> 5) & 63, tile = t >> 11;  // tile < 256
    const uint32_t kc = tile & 63, nb = tile >> 6;
    const uint32_t g = l >> 2, q = l & 3, ks = s >> 4, ntg = s & 15;
    const uint32_t n  = nb * 128 + ntg * 8 + g;
    const uint32_t k0 = kc * 64 + ks * 16 + 2 * q;
    const float b0a = X[(size_t)k0 * DD + n];
    const float b0b = X[(size_t)(k0 + 1) * DD + n];
    const float b1a = X[(size_t)(k0 + 8) * DD + n];
    const float b1b = X[(size_t)(k0 + 9) * DD + n];
    const size_t off = (size_t)tile * TILE_B + s * 256 + l * 8;
    *(uint2*)((char*)g_Xt_hi + off) = make_uint2(pk(b0a, b0b), pk(b1a, b1b));
    *(uint2*)((char*)g_Xt_lo + off) = make_uint2(pklo(b0a, b0b), pklo(b1a, b1b));
}

// W [n,k] row-major -> packed-B hi/lo (no transpose needed).
__global__ void prepW_kernel(const float* __restrict__ W) {
    const uint32_t t = blockIdx.x * 256 + threadIdx.x;        // < 65,536
    const uint32_t l = t & 31, s = (t >> 5) & 63, tile = t >> 11;  // tile < 32
    const uint32_t kc = tile & 7, nb = tile >> 3;
    const uint32_t g = l >> 2, q = l & 3, ks = s >> 4, ntg = s & 15;
    const uint32_t n  = nb * 128 + ntg * 8 + g;
    const uint32_t k0 = kc * 64 + ks * 16 + 2 * q;
    float2 v0 = *(const float2*)(W + (size_t)n * DD + k0);
    float2 v1 = *(const float2*)(W + (size_t)n * DD + k0 + 8);
    const size_t off = (size_t)tile * TILE_B + s * 256 + l * 8;
    *(uint2*)((char*)g_Whi + off) = make_uint2(pk(v0.x, v0.y), pk(v1.x, v1.y));
    *(uint2*)((char*)g_Wlo + off) = make_uint2(pklo(v0.x, v0.y), pklo(v1.x, v1.y));
}

// Ts^T -> packed-B hi/lo (Tst[n][k] = Ts[k][n]).
__global__ void prepT_kernel() {
    const uint32_t t = blockIdx.x * 256 + threadIdx.x;        // < 524,288
    const uint32_t l = t & 31, s = (t >> 5) & 63, tile = t >> 11;  // tile < 256
    const uint32_t kc = tile & 63, nb = tile >> 6;
    const uint32_t g = l >> 2, q = l & 3, ks = s >> 4, ntg = s & 15;
    const uint32_t n  = nb * 128 + ntg * 8 + g;
    const uint32_t k0 = kc * 64 + ks * 16 + 2 * q;
    const float b0a = g_Ts[(size_t)k0 * DD + n];
    const float b0b = g_Ts[(size_t)(k0 + 1) * DD + n];
    const float b1a = g_Ts[(size_t)(k0 + 8) * DD + n];
    const float b1b = g_Ts[(size_t)(k0 + 9) * DD + n];
    const size_t off = (size_t)tile * TILE_B + s * 256 + l * 8;
    *(uint2*)((char*)g_Tst_hi + off) = make_uint2(pk(b0a, b0b), pk(b1a, b1b));
    *(uint2*)((char*)g_Tst_lo + off) = make_uint2(pklo(b0a, b0b), pklo(b1a, b1b));
}

// ---------------- HMMA GEMM (packed operands; R13 math) ----------------
constexpr int NSTAGE = 3;
constexpr int STAGE_BYTES = 4 * TILE_B;          // Ah,Al,Bh,Bl = 64 KB
constexpr int SMEM_DYN = NSTAGE * STAGE_BYTES;   // 192 KB

// MODE 0: A=A2(KC64), B=Xt(KC64) -> Y packed-A
// MODE 1: A=Y (KC8),  B=W (KC8)  -> g_Ts row-major = ds.*acc
// MODE 2: A=A2(KC64), B=Tst(KC64)-> out = relu(ds.*acc)
template <int MODE>
__global__ void __launch_bounds__(256, 1)
hmma_gemm(float* __restrict__ out2)
{
    constexpr int C = (MODE == 1) ? (DD / 64) : (NN / 64);

    const __nv_bfloat16* Ah = (MODE == 1) ? g_Yhi : g_Ahi;
    const __nv_bfloat16* Al = (MODE == 1) ? g_Ylo : g_Alo;
    const __nv_bfloat16* Bh = (MODE == 0) ? g_Xt_hi : (MODE == 1) ? g_Whi : g_Tst_hi;
    const __nv_bfloat16* Bl = (MODE == 0) ? g_Xt_lo : (MODE == 1) ? g_Wlo : g_Tst_lo;

    extern __shared__ char smem_raw[];
    const uint32_t sb32 = smem_u32(smem_raw);

    const int tid  = threadIdx.x;
    const int lane = tid & 31;
    const int wid  = tid >> 5;
    const int mb = blockIdx.y;          // m0 = mb*128
    const int nb = blockIdx.x;          // n0 = nb*128

    // loader: tile t = tid>>6 (0:Ah 1:Al 2:Bh 3:Bl), thread copies 256B contiguous
    const int t = tid >> 6;
    const int u = tid & 63;
    const char* base =
        (t == 0) ? (const char*)Ah + (size_t)mb * C * TILE_B :
        (t == 1) ? (const char*)Al + (size_t)mb * C * TILE_B :
        (t == 2) ? (const char*)Bh + (size_t)nb * C * TILE_B :
                   (const char*)Bl + (size_t)nb * C * TILE_B;
    const uint32_t wdst = sb32 + (uint32_t)t * TILE_B + (uint32_t)u * 256;

    auto load_stage = [&](int stage, int c) {
        const uint32_t d = wdst + (uint32_t)stage * STAGE_BYTES;
        const char* g = base + (size_t)c * TILE_B + u * 256;
        #pragma unroll
        for (int ch = 0; ch < 16; ch++) cp16(d + ch * 16, g + ch * 16);
    };

    #pragma unroll
    for (int i = 0; i < NSTAGE; i++) {
        if (i < C) load_stage(i, i);
        cp_commit();
    }

    // 8 warps = 2(m) x 4(n); warp tile 64x32
    const int wm = (wid >> 2) * 64;     // 0 or 64
    const int wn = (wid & 3) * 32;      // 0,32,64,96
    const int g  = lane >> 2;
    const int q  = lane & 3;
    const uint32_t mtg0 = (uint32_t)(wm >> 4);   // 0 or 4
    const uint32_t ntg0 = (uint32_t)(wn >> 3);   // 0,4,8,12

    float acc[4][4][4];
    #pragma unroll
    for (int a = 0; a < 4; a++)
        #pragma unroll
        for (int b = 0; b < 4; b++)
            #pragma unroll
            for (int r = 0; r < 4; r++) acc[a][b][r] = 0.0f;

    for (int c = 0; c < C; c++) {
        const int s = c % NSTAGE;
        cp_wait<NSTAGE - 1>();
        __syncthreads();
        const uint32_t soff = (uint32_t)s * STAGE_BYTES;

        #pragma unroll
        for (int ks = 0; ks < 4; ks++) {
            uint4 ahv[4], alv[4];
            uint2 bhv[4], blv[4];
            #pragma unroll
            for (int mt = 0; mt < 4; mt++) {
                const uint32_t o = soff + ((ks * 8 + mtg0 + mt) * 32 + lane) * 16;
                ahv[mt] = *(const uint4*)(smem_raw + o);
                alv[mt] = *(const uint4*)(smem_raw + TILE_B + o);
            }
            #pragma unroll
            for (int nt = 0; nt < 4; nt++) {
                const uint32_t o = soff + ((ks * 16 + ntg0 + nt) * 32 + lane) * 8;
                bhv[nt] = *(const uint2*)(smem_raw + 2 * TILE_B + o);
                blv[nt] = *(const uint2*)(smem_raw + 3 * TILE_B + o);
            }
            #pragma unroll
            for (int mt = 0; mt < 4; mt++)
                #pragma unroll
                for (int nt = 0; nt < 4; nt++) {
                    mma16816(acc[mt][nt], (const uint32_t*)&ahv[mt], (const uint32_t*)&bhv[nt]);
                    mma16816(acc[mt][nt], (const uint32_t*)&ahv[mt], (const uint32_t*)&blv[nt]);
                    mma16816(acc[mt][nt], (const uint32_t*)&alv[mt], (const uint32_t*)&bhv[nt]);
                }
        }

        __syncthreads();
        if (c + NSTAGE < C) load_stage(s, c + NSTAGE);
        cp_commit();
    }

    if (MODE == 0) {
        // write Y directly in packed-A layout (acc fragments are fragment-ordered)
        #pragma unroll
        for (int mt = 0; mt < 4; mt++) {
            #pragma unroll
            for (int p = 0; p < 2; p++) {
                const float* d0 = acc[mt][2 * p];
                const float* d1 = acc[mt][2 * p + 1];
                const uint32_t kcp = ((uint32_t)(nb * 128 + wn + p * 16)) >> 6;
                const uint32_t ksp = (((uint32_t)(wn + p * 16)) & 63) >> 4;
                const uint32_t tile = (uint32_t)mb * 8 + kcp;
                const size_t off = (size_t)tile * TILE_B +
                                   (ksp * 8 + mtg0 + mt) * 512 + lane * 16;
                *(uint4*)((char*)g_Yhi + off) =
                    make_uint4(pk(d0[0], d0[1]), pk(d0[2], d0[3]),
                               pk(d1[0], d1[1]), pk(d1[2], d1[3]));
                *(uint4*)((char*)g_Ylo + off) =
                    make_uint4(pklo(d0[0], d0[1]), pklo(d0[2], d0[3]),
                               pklo(d1[0], d1[1]), pklo(d1[2], d1[3]));
            }
        }
    } else {
        // row-major epilogue (R13-validated mapping)
        const int m0 = mb * 128, n0 = nb * 128;
        const int l2 = q << 1;
        #pragma unroll
        for (int mt = 0; mt < 4; mt++) {
            const int r0 = m0 + wm + mt * 16 + g;
            const int r1 = r0 + 8;
            const float ds0 = g_ds[r0], ds1 = g_ds[r1];
            #pragma unroll
            for (int nt = 0; nt < 4; nt++) {
                const int cc = n0 + wn + nt * 8 + l2;
                const size_t i0 = (size_t)r0 * DD + cc;
                const size_t i1 = (size_t)r1 * DD + cc;
                const float* a = acc[mt][nt];
                if (MODE == 1) {
                    *(float2*)(g_Ts + i0) = make_float2(a[0] * ds0, a[1] * ds0);
                    *(float2*)(g_Ts + i1) = make_float2(a[2] * ds1, a[3] * ds1);
                } else {
                    *(float2*)(out2 + i0) = make_float2(fmaxf(a[0] * ds0, 0.0f),
                                                        fmaxf(a[1] * ds0, 0.0f));
                    *(float2*)(out2 + i1) = make_float2(fmaxf(a[2] * ds1, 0.0f),
                                                        fmaxf(a[3] * ds1, 0.0f));
                }
            }
        }
    }
}

// ---------------- host launcher ----------------
extern "C" void kernel_launch(void* const* d_in, const int* in_sizes, int n_in,
                              void* d_out, int out_size)
{
    const float* X = (const float*)d_in[0];  // [4096, 512]
    const float* A = (const float*)d_in[1];  // [4096, 4096]
    const float* W = (const float*)d_in[2];  // [512, 512]
    float* out = (float*)d_out;              // [4096, 512]

    cudaFuncSetAttribute(hmma_gemm<0>, cudaFuncAttributeMaxDynamicSharedMemorySize, SMEM_DYN);
    cudaFuncSetAttribute(hmma_gemm<1>, cudaFuncAttributeMaxDynamicSharedMemorySize, SMEM_DYN);
    cudaFuncSetAttribute(hmma_gemm<2>, cudaFuncAttributeMaxDynamicSharedMemorySize, SMEM_DYN);

    conv_A_kernel<<<8192, 256>>>(A);          // launch 0
    prepXds_kernel<<<2064, 256>>>(X, A);      // launch 1 (+ds tail)
    prepW_kernel<<<256, 256>>>(W);            // launch 2

    dim3 grid(DD / 128, NN / 128);  // (4, 32) = 128 CTAs
    hmma_gemm<0><<<grid, 256, SMEM_DYN>>>(nullptr);  // launch 3  (profiled slot)
    hmma_gemm<1><<<grid, 256, SMEM_DYN>>>(nullptr);  // launch 4
    prepT_kernel<<<2048, 256>>>();                    // launch 5
    hmma_gemm<2><<<grid, 256, SMEM_DYN>>>(out);      // launch 6
}